// round 3
// baseline (speedup 1.0000x reference)
#include <cuda_runtime.h>

#define NN 100000
#define NE 1600000
#define HID 64

// ---- scratch (device globals: allocation-free) ----
__device__ int   g_is64;            // 1 if edge_index buffer is int64
__device__ int   g_es[NE];          // raw src
__device__ int   g_ed[NE];          // raw dst
__device__ int   g_esrc[NE];        // dst-sorted src (CSR payload)
__device__ float g_enorm[NE];       // dst-sorted edge norm
__device__ int   g_cnt[NN];         // in-degree (excl. self-loop)
__device__ int   g_off[NN];         // CSR row start
__device__ int   g_cur[NN];         // bucket cursor
__device__ float g_dinv[NN];        // 1/sqrt(deg), deg = cnt+1
__device__ int   g_bsum[128];       // scan block sums
__device__ int   g_bpre[128];       // scanned block sums
__device__ __align__(16) float g_H[NN * HID];   // h = X @ W
__device__ __align__(16) float g_XA[NN * HID];  // ping-pong post-ReLU feats
__device__ __align__(16) float g_XB[NN * HID];

__device__ __forceinline__ int clampi(int v, int hi) {
    return v < 0 ? 0 : (v >= hi ? hi - 1 : v);
}

// ---------------------------------------------------------------------------
// Detect edge_index dtype: int64 buffers (values < 2^31) have all-zero odd
// 32-bit words; int32 buffers have random node ids there.
// ---------------------------------------------------------------------------
__global__ void k_detect(const unsigned* __restrict__ ei32) {  // 1 block, 256 thr
    __shared__ int nz;
    if (threadIdx.x == 0) nz = 0;
    __syncthreads();
    int any = 0;
    for (int i = threadIdx.x; i < 2048; i += 256)
        if (ei32[2 * i + 1] != 0u) any = 1;
    if (any) atomicOr(&nz, 1);
    __syncthreads();
    if (threadIdx.x == 0) g_is64 = nz ? 0 : 1;
}

__global__ void k_zero() {
    int i = blockIdx.x * blockDim.x + threadIdx.x;
    if (i < NN) { g_cnt[i] = 0; g_cur[i] = 0; }
}

__global__ void k_count(const void* __restrict__ eiv) {
    int e = blockIdx.x * blockDim.x + threadIdx.x;
    if (e >= NE) return;
    int s, d;
    if (g_is64) {
        const long long* ei = (const long long*)eiv;
        s = (int)ei[e];
        d = (int)ei[NE + e];
    } else {
        const int* ei = (const int*)eiv;
        s = ei[e];
        d = ei[NE + e];
    }
    s = clampi(s, NN);
    d = clampi(d, NN);
    g_es[e] = s;
    g_ed[e] = d;
    atomicAdd(&g_cnt[d], 1);
}

// exclusive scan of g_cnt -> g_off
__global__ void k_scan1() {              // grid 98, block 1024
    __shared__ int sm[1024];
    int i = blockIdx.x * 1024 + threadIdx.x;
    int v = (i < NN) ? g_cnt[i] : 0;
    sm[threadIdx.x] = v;
    __syncthreads();
#pragma unroll
    for (int ofs = 1; ofs < 1024; ofs <<= 1) {
        int t = (threadIdx.x >= ofs) ? sm[threadIdx.x - ofs] : 0;
        __syncthreads();
        sm[threadIdx.x] += t;
        __syncthreads();
    }
    if (i < NN) g_off[i] = sm[threadIdx.x] - v;     // exclusive
    if (threadIdx.x == 1023) g_bsum[blockIdx.x] = sm[1023];
}

__global__ void k_scan2() {              // 1 block, 128 threads
    __shared__ int sm[128];
    int v = (threadIdx.x < 98) ? g_bsum[threadIdx.x] : 0;
    sm[threadIdx.x] = v;
    __syncthreads();
#pragma unroll
    for (int ofs = 1; ofs < 128; ofs <<= 1) {
        int t = (threadIdx.x >= ofs) ? sm[threadIdx.x - ofs] : 0;
        __syncthreads();
        sm[threadIdx.x] += t;
        __syncthreads();
    }
    g_bpre[threadIdx.x] = sm[threadIdx.x] - v;      // exclusive
}

__global__ void k_scan3() {              // grid 98, block 1024
    int i = blockIdx.x * 1024 + threadIdx.x;
    if (i < NN) {
        g_off[i] += g_bpre[blockIdx.x];
        g_dinv[i] = rsqrtf((float)(g_cnt[i] + 1)); // +1 self-loop
    }
}

__global__ void k_bucket() {
    int e = blockIdx.x * blockDim.x + threadIdx.x;
    if (e >= NE) return;
    int s = g_es[e], d = g_ed[e];
    int pos = g_off[d] + atomicAdd(&g_cur[d], 1);
    pos = clampi(pos, NE);
    g_esrc[pos]  = s;
    g_enorm[pos] = g_dinv[s] * g_dinv[d];
}

// ---------------------------------------------------------------------------
// GEMM: H = X @ W.  256 thr/block = 16 rows; thread -> (row, 4-col group).
// ---------------------------------------------------------------------------
__global__ void k_gemm(const float* __restrict__ xext, int sel,
                       const float* __restrict__ W) {
    const float* xin = (sel == 0) ? xext : ((sel == 1) ? g_XA : g_XB);

    __shared__ float4 sW[HID * HID / 4];            // 16 KB
    const float4* W4 = (const float4*)W;
    for (int i = threadIdx.x; i < HID * HID / 4; i += blockDim.x)
        sW[i] = W4[i];
    __syncthreads();

    const int t   = threadIdx.x;
    const int tg  = t & 15;
    const int row = blockIdx.x * 16 + (t >> 4);     // NN % 16 == 0

    const float4* xrow = (const float4*)(xin + (size_t)row * HID);

    float4 acc = make_float4(0.f, 0.f, 0.f, 0.f);
#pragma unroll
    for (int kq = 0; kq < 16; kq++) {
        float4 xv = __ldg(&xrow[kq]);
        float4 w;
        w = sW[(4 * kq + 0) * 16 + tg];
        acc.x += xv.x * w.x; acc.y += xv.x * w.y; acc.z += xv.x * w.z; acc.w += xv.x * w.w;
        w = sW[(4 * kq + 1) * 16 + tg];
        acc.x += xv.y * w.x; acc.y += xv.y * w.y; acc.z += xv.y * w.z; acc.w += xv.y * w.w;
        w = sW[(4 * kq + 2) * 16 + tg];
        acc.x += xv.z * w.x; acc.y += xv.z * w.y; acc.z += xv.z * w.z; acc.w += xv.z * w.w;
        w = sW[(4 * kq + 3) * 16 + tg];
        acc.x += xv.w * w.x; acc.y += xv.w * w.y; acc.z += xv.w * w.z; acc.w += xv.w * w.w;
    }
    ((float4*)g_H)[row * 16 + tg] = acc;
}

// ---------------------------------------------------------------------------
// Aggregate: one warp per node, atomic-free gather over CSR in-edges.
//   Y = b + dinv^2*H[node] + sum_e H[src_e]*norm_e + (resid? Xprev[node] : 0)
//   Xnext[node] = relu(Y)   (stored post-ReLU -> feeds next layer directly)
// ---------------------------------------------------------------------------
__global__ void k_agg(const float* __restrict__ xext, int sel, int osel,
                      const float* __restrict__ b, int resid) {
    const float* Xp = (sel == 0) ? xext : ((sel == 1) ? g_XA : g_XB);
    float* Xn = (osel == 1) ? g_XA : g_XB;

    int gid  = blockIdx.x * blockDim.x + threadIdx.x;
    int node = gid >> 5;
    int lane = gid & 31;

    float dv = g_dinv[node];
    float d2 = dv * dv;
    float a0 = g_H[(size_t)node * 64 + lane]      * d2;
    float a1 = g_H[(size_t)node * 64 + 32 + lane] * d2;
    if (resid) {
        a0 += Xp[(size_t)node * 64 + lane];
        a1 += Xp[(size_t)node * 64 + 32 + lane];
    }

    int off = g_off[node];
    int k   = g_cnt[node];
    for (int i = 0; i < k; i += 32) {
        int   in = i + lane < k;
        int   si = in ? g_esrc[off + i + lane]  : 0;
        float nm = in ? g_enorm[off + i + lane] : 0.f;
        int lim = min(32, k - i);
        for (int j = 0; j < lim; j++) {
            int   s = __shfl_sync(0xffffffffu, si, j);
            float w = __shfl_sync(0xffffffffu, nm, j);
            a0 += g_H[(size_t)s * 64 + lane]      * w;
            a1 += g_H[(size_t)s * 64 + 32 + lane] * w;
        }
    }

    float b0 = __ldg(&b[lane]);
    float b1 = __ldg(&b[32 + lane]);
    Xn[(size_t)node * 64 + lane]      = fmaxf(a0 + b0, 0.f);
    Xn[(size_t)node * 64 + 32 + lane] = fmaxf(a1 + b1, 0.f);
}

// ---------------------------------------------------------------------------
// Classifier: out = X @ Wc + bc   (X already post-ReLU), one warp per node.
// ---------------------------------------------------------------------------
__global__ void k_classify(int sel,
                           const float* __restrict__ Wc,   // [64,3]
                           const float* __restrict__ bc,   // [3]
                           float* __restrict__ out) {
    const float* X = (sel == 1) ? g_XA : g_XB;
    int gid  = blockIdx.x * blockDim.x + threadIdx.x;
    int node = gid >> 5;
    int lane = gid & 31;

    float x0 = X[(size_t)node * 64 + lane];
    float x1 = X[(size_t)node * 64 + 32 + lane];

    float c0 = x0 * __ldg(&Wc[lane * 3 + 0]) + x1 * __ldg(&Wc[(lane + 32) * 3 + 0]);
    float c1 = x0 * __ldg(&Wc[lane * 3 + 1]) + x1 * __ldg(&Wc[(lane + 32) * 3 + 1]);
    float c2 = x0 * __ldg(&Wc[lane * 3 + 2]) + x1 * __ldg(&Wc[(lane + 32) * 3 + 2]);

#pragma unroll
    for (int o = 16; o > 0; o >>= 1) {
        c0 += __shfl_down_sync(0xffffffffu, c0, o);
        c1 += __shfl_down_sync(0xffffffffu, c1, o);
        c2 += __shfl_down_sync(0xffffffffu, c2, o);
    }
    if (lane == 0) {
        out[node * 3 + 0] = c0 + __ldg(&bc[0]);
        out[node * 3 + 1] = c1 + __ldg(&bc[1]);
        out[node * 3 + 2] = c2 + __ldg(&bc[2]);
    }
}

// ---------------------------------------------------------------------------
extern "C" void kernel_launch(void* const* d_in, const int* in_sizes, int n_in,
                              void* d_out, int out_size) {
    const float* x  = (const float*)d_in[0];
    const void*  ei = d_in[1];
    const float* Ws = (const float*)d_in[2];
    const float* bs = (const float*)d_in[3];
    const float* Wc = (const float*)d_in[4];
    const float* bc = (const float*)d_in[5];
    float* out = (float*)d_out;

    // ---- CSR build (amortized over 4 layers) ----
    k_detect<<<1, 256>>>((const unsigned*)ei);
    k_zero  <<<(NN + 255) / 256, 256>>>();
    k_count <<<NE / 256, 256>>>(ei);
    k_scan1 <<<98, 1024>>>();
    k_scan2 <<<1, 128>>>();
    k_scan3 <<<98, 1024>>>();
    k_bucket<<<NE / 256, 256>>>();

    // ---- 4 GCN layers ----
    int sel = 0;                                    // 0=x, 1=g_XA, 2=g_XB
    for (int l = 0; l < 4; l++) {
        int osel = (l & 1) ? 2 : 1;
        const float* W = Ws + l * HID * HID;
        const float* b = bs + l * HID;
        k_gemm<<<NN / 16, 256>>>(x, sel, W);
        k_agg <<<NN * 32 / 256, 256>>>(x, sel, osel, b, (l > 0) ? 1 : 0);
        sel = osel;
    }

    // ---- classifier head ----
    k_classify<<<NN * 32 / 256, 256>>>(sel, Wc, bc, out);
}

// round 4
// speedup vs baseline: 1.4907x; 1.4907x over previous
#include <cuda_runtime.h>

#define NN 100000
#define NE 1600000
#define HID 64

// ---- scratch (device globals: allocation-free) ----
__device__ int   g_is64;                         // 1 if edge_index is int64
__device__ __align__(16) int2  g_e[NE];          // raw (src, dst)
__device__ __align__(16) int2  g_eadj[NE];       // dst-sorted (src, norm bits)
__device__ int   g_cnt[NN];                      // in-degree (excl. self-loop)
__device__ int   g_off[NN];                      // CSR row start
__device__ int   g_cur[NN];                      // bucket cursor
__device__ float g_dinv[NN];                     // 1/sqrt(deg), deg = cnt+1
__device__ int   g_bsum[128];
__device__ int   g_bpre[128];
__device__ __align__(16) float g_H[NN * HID];    // h = X @ W
__device__ __align__(16) float g_XA[NN * HID];   // ping-pong feature buffers
__device__ __align__(16) float g_XB[NN * HID];

__device__ __forceinline__ int clampi(int v, int hi) {
    return v < 0 ? 0 : (v >= hi ? hi - 1 : v);
}

__device__ __forceinline__ unsigned long long pack2(float f) {
    unsigned long long r;
    asm("mov.b64 %0, {%1, %1};" : "=l"(r) : "f"(f));
    return r;
}
__device__ __forceinline__ unsigned long long ffma2(unsigned long long a,
                                                    unsigned long long b,
                                                    unsigned long long c) {
    unsigned long long d;
    asm("fma.rn.f32x2 %0, %1, %2, %3;" : "=l"(d) : "l"(a), "l"(b), "l"(c));
    return d;
}
__device__ __forceinline__ void unpack2(unsigned long long v, float& lo, float& hi) {
    asm("mov.b64 {%0, %1}, %2;" : "=f"(lo), "=f"(hi) : "l"(v));
}

// ---------------------------------------------------------------------------
// edge_index dtype detection (int64 odd words are all zero for ids < 2^31)
// ---------------------------------------------------------------------------
__global__ void k_detect(const unsigned* __restrict__ ei32) {   // 1 blk, 256 thr
    __shared__ int nz;
    if (threadIdx.x == 0) nz = 0;
    __syncthreads();
    int any = 0;
    for (int i = threadIdx.x; i < 2048; i += 256)
        if (ei32[2 * i + 1] != 0u) any = 1;
    if (any) atomicOr(&nz, 1);
    __syncthreads();
    if (threadIdx.x == 0) g_is64 = nz ? 0 : 1;
}

__global__ void k_zero() {
    int i = blockIdx.x * blockDim.x + threadIdx.x;
    if (i < NN) { g_cnt[i] = 0; g_cur[i] = 0; }
}

__global__ void k_count(const void* __restrict__ eiv) {
    int e = blockIdx.x * blockDim.x + threadIdx.x;
    if (e >= NE) return;
    int s, d;
    if (g_is64) {
        const long long* ei = (const long long*)eiv;
        s = (int)ei[e];
        d = (int)ei[NE + e];
    } else {
        const int* ei = (const int*)eiv;
        s = ei[e];
        d = ei[NE + e];
    }
    s = clampi(s, NN);
    d = clampi(d, NN);
    g_e[e] = make_int2(s, d);
    atomicAdd(&g_cnt[d], 1);
}

// exclusive scan of g_cnt -> g_off
__global__ void k_scan1() {              // grid 98, block 1024
    __shared__ int sm[1024];
    int i = blockIdx.x * 1024 + threadIdx.x;
    int v = (i < NN) ? g_cnt[i] : 0;
    sm[threadIdx.x] = v;
    __syncthreads();
#pragma unroll
    for (int ofs = 1; ofs < 1024; ofs <<= 1) {
        int t = (threadIdx.x >= ofs) ? sm[threadIdx.x - ofs] : 0;
        __syncthreads();
        sm[threadIdx.x] += t;
        __syncthreads();
    }
    if (i < NN) g_off[i] = sm[threadIdx.x] - v;
    if (threadIdx.x == 1023) g_bsum[blockIdx.x] = sm[1023];
}

__global__ void k_scan2() {              // 1 block, 128 threads
    __shared__ int sm[128];
    int v = (threadIdx.x < 98) ? g_bsum[threadIdx.x] : 0;
    sm[threadIdx.x] = v;
    __syncthreads();
#pragma unroll
    for (int ofs = 1; ofs < 128; ofs <<= 1) {
        int t = (threadIdx.x >= ofs) ? sm[threadIdx.x - ofs] : 0;
        __syncthreads();
        sm[threadIdx.x] += t;
        __syncthreads();
    }
    g_bpre[threadIdx.x] = sm[threadIdx.x] - v;
}

__global__ void k_scan3() {              // grid 98, block 1024
    int i = blockIdx.x * 1024 + threadIdx.x;
    if (i < NN) {
        g_off[i] += g_bpre[blockIdx.x];
        g_dinv[i] = rsqrtf((float)(g_cnt[i] + 1));
    }
}

__global__ void k_bucket() {
    int e = blockIdx.x * blockDim.x + threadIdx.x;
    if (e >= NE) return;
    int2 sd = g_e[e];
    int pos = g_off[sd.y] + atomicAdd(&g_cur[sd.y], 1);
    pos = clampi(pos, NE);
    float nm = g_dinv[sd.x] * g_dinv[sd.y];
    g_eadj[pos] = make_int2(sd.x, __float_as_int(nm));
}

// ---------------------------------------------------------------------------
// GEMM + epilogue:  H = X @ W ;  Yinit = b + dinv^2 * H + (resid ? X : 0)
// 256 thr/block, 64 rows/block. Thread: 4 rows x 4 cols, FFMA2 packed math.
// ---------------------------------------------------------------------------
__global__ void k_gemm(const float* __restrict__ xext, int xsel,
                       const float* __restrict__ W,
                       const float* __restrict__ bias,
                       int ysel, int resid) {
    const float* xin = (xsel == 0) ? xext : ((xsel == 1) ? g_XA : g_XB);
    float* Y = (ysel == 1) ? g_XA : g_XB;

    __shared__ ulonglong2 sW[HID * 16];              // 16 KB; {cols01, cols23}
    const ulonglong2* Wp = (const ulonglong2*)W;
    for (int i = threadIdx.x; i < HID * 16; i += 256) sW[i] = Wp[i];
    __syncthreads();

    const int cg   = threadIdx.x & 15;               // 4-col group
    const int rq   = threadIdx.x >> 4;               // 0..15
    const int row0 = blockIdx.x * 64 + rq * 4;

    const float4* xr[4];
#pragma unroll
    for (int r = 0; r < 4; r++) {
        int rc = clampi(row0 + r, NN);
        xr[r] = (const float4*)(xin + (size_t)rc * HID);
    }

    unsigned long long a01[4] = {0, 0, 0, 0};        // cols (4cg, 4cg+1)
    unsigned long long a23[4] = {0, 0, 0, 0};        // cols (4cg+2, 4cg+3)

#pragma unroll
    for (int kq = 0; kq < 16; kq++) {
        float4 xv0 = __ldg(&xr[0][kq]);
        float4 xv1 = __ldg(&xr[1][kq]);
        float4 xv2 = __ldg(&xr[2][kq]);
        float4 xv3 = __ldg(&xr[3][kq]);
#define GSTEP(J, C) { \
        ulonglong2 w = sW[(4 * kq + (J)) * 16 + cg]; \
        unsigned long long xx; \
        xx = pack2(xv0.C); a01[0] = ffma2(xx, w.x, a01[0]); a23[0] = ffma2(xx, w.y, a23[0]); \
        xx = pack2(xv1.C); a01[1] = ffma2(xx, w.x, a01[1]); a23[1] = ffma2(xx, w.y, a23[1]); \
        xx = pack2(xv2.C); a01[2] = ffma2(xx, w.x, a01[2]); a23[2] = ffma2(xx, w.y, a23[2]); \
        xx = pack2(xv3.C); a01[3] = ffma2(xx, w.x, a01[3]); a23[3] = ffma2(xx, w.y, a23[3]); }
        GSTEP(0, x) GSTEP(1, y) GSTEP(2, z) GSTEP(3, w)
#undef GSTEP
    }

    const float4 b4 = __ldg(&((const float4*)bias)[cg]);
#pragma unroll
    for (int r = 0; r < 4; r++) {
        int row = row0 + r;
        if (row < NN) {
            float4 h;
            unpack2(a01[r], h.x, h.y);
            unpack2(a23[r], h.z, h.w);
            ((float4*)g_H)[(size_t)row * 16 + cg] = h;
            float dv = g_dinv[row];
            float d2 = dv * dv;
            float4 y = make_float4(b4.x + h.x * d2, b4.y + h.y * d2,
                                   b4.z + h.z * d2, b4.w + h.w * d2);
            if (resid) {
                float4 xv = __ldg(&xr[r][cg]);   // input is already post-ReLU
                y.x += xv.x; y.y += xv.y; y.z += xv.z; y.w += xv.w;
            }
            ((float4*)Y)[(size_t)row * 16 + cg] = y;
        }
    }
}

// ---------------------------------------------------------------------------
// Aggregate: one warp per node, atomic-free CSR gather.
//   a = Yinit[node] + sum_e H[src_e] * norm_e ;  X = relu(a)
// Final layer (classify=1): out[node] = X @ Wc + bc instead of storing X.
// ---------------------------------------------------------------------------
__global__ void k_agg(int ysel,
                      const float* __restrict__ Wc,
                      const float* __restrict__ bc,
                      float* __restrict__ out, int classify) {
    float* Y = (ysel == 1) ? g_XA : g_XB;
    int gid  = blockIdx.x * blockDim.x + threadIdx.x;
    int node = gid >> 5;
    int lane = gid & 31;

    float2 a = ((float2*)Y)[(size_t)node * 32 + lane];

    const int2* adj = g_eadj + g_off[node];
    int k = g_cnt[node];
    const float2* H2 = (const float2*)g_H;

#pragma unroll 4
    for (int j = 0; j < k; j++) {
        int2 e = __ldg(&adj[j]);                 // broadcast (uniform addr)
        float w = __int_as_float(e.y);
        float2 h = __ldg(&H2[(size_t)e.x * 32 + lane]);
        a.x += h.x * w;
        a.y += h.y * w;
    }

    a.x = fmaxf(a.x, 0.f);
    a.y = fmaxf(a.y, 0.f);

    if (!classify) {
        ((float2*)Y)[(size_t)node * 32 + lane] = a;
    } else {
        int f = 2 * lane;                        // features f, f+1
        float c0 = a.x * __ldg(&Wc[f * 3 + 0]) + a.y * __ldg(&Wc[f * 3 + 3]);
        float c1 = a.x * __ldg(&Wc[f * 3 + 1]) + a.y * __ldg(&Wc[f * 3 + 4]);
        float c2 = a.x * __ldg(&Wc[f * 3 + 2]) + a.y * __ldg(&Wc[f * 3 + 5]);
#pragma unroll
        for (int o = 16; o > 0; o >>= 1) {
            c0 += __shfl_down_sync(0xffffffffu, c0, o);
            c1 += __shfl_down_sync(0xffffffffu, c1, o);
            c2 += __shfl_down_sync(0xffffffffu, c2, o);
        }
        if (lane == 0) {
            out[node * 3 + 0] = c0 + __ldg(&bc[0]);
            out[node * 3 + 1] = c1 + __ldg(&bc[1]);
            out[node * 3 + 2] = c2 + __ldg(&bc[2]);
        }
    }
}

// ---------------------------------------------------------------------------
extern "C" void kernel_launch(void* const* d_in, const int* in_sizes, int n_in,
                              void* d_out, int out_size) {
    const float* x  = (const float*)d_in[0];
    const void*  ei = d_in[1];
    const float* Ws = (const float*)d_in[2];
    const float* bs = (const float*)d_in[3];
    const float* Wc = (const float*)d_in[4];
    const float* bc = (const float*)d_in[5];
    float* out = (float*)d_out;

    // ---- CSR build ----
    k_detect<<<1, 256>>>((const unsigned*)ei);
    k_zero  <<<(NN + 255) / 256, 256>>>();
    k_count <<<NE / 256, 256>>>(ei);
    k_scan1 <<<98, 1024>>>();
    k_scan2 <<<1, 128>>>();
    k_scan3 <<<98, 1024>>>();
    k_bucket<<<NE / 256, 256>>>();

    // ---- 4 GCN layers (layer 3 fuses the classifier) ----
    const int gemm_grid = (NN + 63) / 64;
    const int agg_grid  = NN * 32 / 256;
    int sel = 0;                                    // 0=x, 1=g_XA, 2=g_XB
    for (int l = 0; l < 4; l++) {
        int osel = (l & 1) ? 2 : 1;
        const float* W = Ws + l * HID * HID;
        const float* b = bs + l * HID;
        k_gemm<<<gemm_grid, 256>>>(x, sel, W, b, osel, (l > 0) ? 1 : 0);
        k_agg <<<agg_grid, 256>>>(osel, Wc, bc, out, (l == 3) ? 1 : 0);
        sel = osel;
    }
}

// round 5
// speedup vs baseline: 1.6463x; 1.1043x over previous
#include <cuda_runtime.h>
#include <cuda_fp16.h>

#define NN 100000
#define NE 1600000
#define HID 64

// ---- scratch (device globals: allocation-free) ----
__device__ int   g_is64;                          // 1 if edge_index is int64
__device__ __align__(16) int2  g_eadj[NE];        // dst-sorted (src, norm bits)
__device__ int   g_cnt[NN];                       // in-degree (excl. self-loop)
__device__ int   g_off[NN];                       // CSR row start
__device__ int   g_cur[NN];                       // bucket cursor
__device__ float g_dinv[NN];                      // 1/sqrt(deg), deg = cnt+1
__device__ int   g_bsum[128];
__device__ __align__(16) __half g_Hh[NN * HID];   // h = X @ W   (fp16 gather copy)
__device__ __align__(16) float  g_XA[NN * HID];   // ping-pong feature buffers
__device__ __align__(16) float  g_XB[NN * HID];

__device__ __forceinline__ int clampi(int v, int hi) {
    return v < 0 ? 0 : (v >= hi ? hi - 1 : v);
}

__device__ __forceinline__ unsigned long long pack2(float f) {
    unsigned long long r;
    asm("mov.b64 %0, {%1, %1};" : "=l"(r) : "f"(f));
    return r;
}
__device__ __forceinline__ unsigned long long ffma2(unsigned long long a,
                                                    unsigned long long b,
                                                    unsigned long long c) {
    unsigned long long d;
    asm("fma.rn.f32x2 %0, %1, %2, %3;" : "=l"(d) : "l"(a), "l"(b), "l"(c));
    return d;
}
__device__ __forceinline__ void unpack2(unsigned long long v, float& lo, float& hi) {
    asm("mov.b64 {%0, %1}, %2;" : "=f"(lo), "=f"(hi) : "l"(v));
}

// ---------------------------------------------------------------------------
// Init: zero counters; block 0 also detects edge_index dtype (int64 buffers
// with ids < 2^31 have all-zero odd 32-bit words).
// ---------------------------------------------------------------------------
__global__ void k_init(const unsigned* __restrict__ ei32) {   // grid 391, 256
    int i = blockIdx.x * 256 + threadIdx.x;
    if (i < NN) { g_cnt[i] = 0; g_cur[i] = 0; }
    if (blockIdx.x == 0) {
        int any = 0;
        for (int j = threadIdx.x; j < 2048; j += 256)
            if (ei32[2 * j + 1] != 0u) any = 1;
        any = __syncthreads_or(any);
        if (threadIdx.x == 0) g_is64 = any ? 0 : 1;
    }
}

__global__ void k_count(const void* __restrict__ eiv) {
    int e = blockIdx.x * blockDim.x + threadIdx.x;
    if (e >= NE) return;
    int d;
    if (g_is64) d = (int)((const long long*)eiv)[NE + e];
    else        d = ((const int*)eiv)[NE + e];
    atomicAdd(&g_cnt[clampi(d, NN)], 1);
}

// exclusive scan of g_cnt -> g_off (warp-shuffle scans)
__global__ void k_scan1() {              // grid 98, block 1024
    __shared__ int wsum[32];
    int i    = blockIdx.x * 1024 + threadIdx.x;
    int lane = threadIdx.x & 31, wid = threadIdx.x >> 5;
    int v   = (i < NN) ? g_cnt[i] : 0;
    int inc = v;
#pragma unroll
    for (int o = 1; o < 32; o <<= 1) {
        int t = __shfl_up_sync(0xffffffffu, inc, o);
        if (lane >= o) inc += t;
    }
    if (lane == 31) wsum[wid] = inc;
    __syncthreads();
    if (wid == 0) {
        int s = wsum[lane];
        int si = s;
#pragma unroll
        for (int o = 1; o < 32; o <<= 1) {
            int t = __shfl_up_sync(0xffffffffu, si, o);
            if (lane >= o) si += t;
        }
        wsum[lane] = si - s;                       // exclusive warp prefix
    }
    __syncthreads();
    if (i < NN) g_off[i] = wsum[wid] + inc - v;    // block-local exclusive
    if (threadIdx.x == 1023) g_bsum[blockIdx.x] = wsum[31] + inc;  // block total
}

__global__ void k_scan2() {              // 1 block, 128 threads
    __shared__ int wsum[4];
    int lane = threadIdx.x & 31, wid = threadIdx.x >> 5;
    int v   = (threadIdx.x < 98) ? g_bsum[threadIdx.x] : 0;
    int inc = v;
#pragma unroll
    for (int o = 1; o < 32; o <<= 1) {
        int t = __shfl_up_sync(0xffffffffu, inc, o);
        if (lane >= o) inc += t;
    }
    if (lane == 31) wsum[wid] = inc;
    __syncthreads();
    int wpre = 0;
#pragma unroll
    for (int w = 0; w < 4; w++)
        if (w < wid) wpre += wsum[w];
    g_bsum[threadIdx.x] = wpre + inc - v;          // exclusive (in-place)
}

__global__ void k_scan3() {              // grid 98, block 1024
    int i = blockIdx.x * 1024 + threadIdx.x;
    if (i < NN) {
        g_off[i] += g_bsum[blockIdx.x];
        g_dinv[i] = rsqrtf((float)(g_cnt[i] + 1));
    }
}

__global__ void k_bucket(const void* __restrict__ eiv) {
    int e = blockIdx.x * blockDim.x + threadIdx.x;
    if (e >= NE) return;
    int s, d;
    if (g_is64) {
        const long long* ei = (const long long*)eiv;
        s = (int)ei[e];
        d = (int)ei[NE + e];
    } else {
        const int* ei = (const int*)eiv;
        s = ei[e];
        d = ei[NE + e];
    }
    s = clampi(s, NN);
    d = clampi(d, NN);
    int pos = g_off[d] + atomicAdd(&g_cur[d], 1);
    pos = clampi(pos, NE);
    float nm = g_dinv[s] * g_dinv[d];
    g_eadj[pos] = make_int2(s, __float_as_int(nm));
}

// ---------------------------------------------------------------------------
// GEMM + epilogue:  H = X @ W (stored fp16 for the gather);
//                   Yinit = b + dinv^2 * H + (resid ? X : 0)   (fp32)
// 256 thr/block, 64 rows/block. Thread: 4 rows x 4 cols, FFMA2 packed math.
// ---------------------------------------------------------------------------
__global__ void k_gemm(const float* __restrict__ xext, int xsel,
                       const float* __restrict__ W,
                       const float* __restrict__ bias,
                       int ysel, int resid) {
    const float* xin = (xsel == 0) ? xext : ((xsel == 1) ? g_XA : g_XB);
    float* Y = (ysel == 1) ? g_XA : g_XB;

    __shared__ ulonglong2 sW[HID * 16];              // 16 KB; {cols01, cols23}
    const ulonglong2* Wp = (const ulonglong2*)W;
    for (int i = threadIdx.x; i < HID * 16; i += 256) sW[i] = Wp[i];
    __syncthreads();

    const int cg   = threadIdx.x & 15;               // 4-col group
    const int rq   = threadIdx.x >> 4;               // 0..15
    const int row0 = blockIdx.x * 64 + rq * 4;

    const float4* xr[4];
#pragma unroll
    for (int r = 0; r < 4; r++) {
        int rc = clampi(row0 + r, NN);
        xr[r] = (const float4*)(xin + (size_t)rc * HID);
    }

    unsigned long long a01[4] = {0, 0, 0, 0};        // cols (4cg, 4cg+1)
    unsigned long long a23[4] = {0, 0, 0, 0};        // cols (4cg+2, 4cg+3)

#pragma unroll
    for (int kq = 0; kq < 16; kq++) {
        float4 xv0 = __ldg(&xr[0][kq]);
        float4 xv1 = __ldg(&xr[1][kq]);
        float4 xv2 = __ldg(&xr[2][kq]);
        float4 xv3 = __ldg(&xr[3][kq]);
#define GSTEP(J, C) { \
        ulonglong2 w = sW[(4 * kq + (J)) * 16 + cg]; \
        unsigned long long xx; \
        xx = pack2(xv0.C); a01[0] = ffma2(xx, w.x, a01[0]); a23[0] = ffma2(xx, w.y, a23[0]); \
        xx = pack2(xv1.C); a01[1] = ffma2(xx, w.x, a01[1]); a23[1] = ffma2(xx, w.y, a23[1]); \
        xx = pack2(xv2.C); a01[2] = ffma2(xx, w.x, a01[2]); a23[2] = ffma2(xx, w.y, a23[2]); \
        xx = pack2(xv3.C); a01[3] = ffma2(xx, w.x, a01[3]); a23[3] = ffma2(xx, w.y, a23[3]); }
        GSTEP(0, x) GSTEP(1, y) GSTEP(2, z) GSTEP(3, w)
#undef GSTEP
    }

    const float4 b4 = __ldg(&((const float4*)bias)[cg]);
#pragma unroll
    for (int r = 0; r < 4; r++) {
        int row = row0 + r;
        if (row < NN) {
            float4 h;
            unpack2(a01[r], h.x, h.y);
            unpack2(a23[r], h.z, h.w);
            // fp16 copy for the gather (one 8B store: 4 halves)
            __half2 p0 = __float22half2_rn(make_float2(h.x, h.y));
            __half2 p1 = __float22half2_rn(make_float2(h.z, h.w));
            uint2 hp;
            hp.x = *(unsigned*)&p0;
            hp.y = *(unsigned*)&p1;
            ((uint2*)g_Hh)[(size_t)row * 16 + cg] = hp;
            // fp32 Y init: bias + self-loop (exact) + residual (exact)
            float dv = g_dinv[row];
            float d2 = dv * dv;
            float4 y = make_float4(b4.x + h.x * d2, b4.y + h.y * d2,
                                   b4.z + h.z * d2, b4.w + h.w * d2);
            if (resid) {
                float4 xv = __ldg(&xr[r][cg]);   // input is already post-ReLU
                y.x += xv.x; y.y += xv.y; y.z += xv.z; y.w += xv.w;
            }
            ((float4*)Y)[(size_t)row * 16 + cg] = y;
        }
    }
}

// ---------------------------------------------------------------------------
// Aggregate: one warp per node, atomic-free CSR gather (fp16 reads, fp32 acc).
//   a = Yinit[node] + sum_e H[src_e] * norm_e ;  X = relu(a)
// Final layer (classify=1): out[node] = X @ Wc + bc instead of storing X.
// ---------------------------------------------------------------------------
__global__ void k_agg(int ysel,
                      const float* __restrict__ Wc,
                      const float* __restrict__ bc,
                      float* __restrict__ out, int classify) {
    float* Y = (ysel == 1) ? g_XA : g_XB;
    int gid  = blockIdx.x * blockDim.x + threadIdx.x;
    int node = gid >> 5;
    int lane = gid & 31;

    float2 a = ((float2*)Y)[(size_t)node * 32 + lane];

    const int2* adj = g_eadj + g_off[node];
    int k = g_cnt[node];
    const __half2* H2 = (const __half2*)g_Hh;

#pragma unroll 4
    for (int j = 0; j < k; j++) {
        int2 e = __ldg(&adj[j]);                 // broadcast (uniform addr)
        float w = __int_as_float(e.y);
        float2 h = __half22float2(__ldg(&H2[(size_t)e.x * 32 + lane]));
        a.x += h.x * w;
        a.y += h.y * w;
    }

    a.x = fmaxf(a.x, 0.f);
    a.y = fmaxf(a.y, 0.f);

    if (!classify) {
        ((float2*)Y)[(size_t)node * 32 + lane] = a;
    } else {
        int f = 2 * lane;                        // features f, f+1
        float c0 = a.x * __ldg(&Wc[f * 3 + 0]) + a.y * __ldg(&Wc[f * 3 + 3]);
        float c1 = a.x * __ldg(&Wc[f * 3 + 1]) + a.y * __ldg(&Wc[f * 3 + 4]);
        float c2 = a.x * __ldg(&Wc[f * 3 + 2]) + a.y * __ldg(&Wc[f * 3 + 5]);
#pragma unroll
        for (int o = 16; o > 0; o >>= 1) {
            c0 += __shfl_down_sync(0xffffffffu, c0, o);
            c1 += __shfl_down_sync(0xffffffffu, c1, o);
            c2 += __shfl_down_sync(0xffffffffu, c2, o);
        }
        if (lane == 0) {
            out[node * 3 + 0] = c0 + __ldg(&bc[0]);
            out[node * 3 + 1] = c1 + __ldg(&bc[1]);
            out[node * 3 + 2] = c2 + __ldg(&bc[2]);
        }
    }
}

// ---------------------------------------------------------------------------
extern "C" void kernel_launch(void* const* d_in, const int* in_sizes, int n_in,
                              void* d_out, int out_size) {
    const float* x  = (const float*)d_in[0];
    const void*  ei = d_in[1];
    const float* Ws = (const float*)d_in[2];
    const float* bs = (const float*)d_in[3];
    const float* Wc = (const float*)d_in[4];
    const float* bc = (const float*)d_in[5];
    float* out = (float*)d_out;

    // ---- CSR build ----
    k_init  <<<(NN + 255) / 256, 256>>>((const unsigned*)ei);
    k_count <<<NE / 256, 256>>>(ei);
    k_scan1 <<<98, 1024>>>();
    k_scan2 <<<1, 128>>>();
    k_scan3 <<<98, 1024>>>();
    k_bucket<<<NE / 256, 256>>>(ei);

    // ---- 4 GCN layers (layer 3 fuses the classifier) ----
    const int gemm_grid = (NN + 63) / 64;
    const int agg_grid  = NN * 32 / 256;
    int sel = 0;                                    // 0=x, 1=g_XA, 2=g_XB
    for (int l = 0; l < 4; l++) {
        int osel = (l & 1) ? 2 : 1;
        const float* W = Ws + l * HID * HID;
        const float* b = bs + l * HID;
        k_gemm<<<gemm_grid, 256>>>(x, sel, W, b, osel, (l > 0) ? 1 : 0);
        k_agg <<<agg_grid, 256>>>(osel, Wc, bc, out, (l == 3) ? 1 : 0);
        sel = osel;
    }
}

// round 6
// speedup vs baseline: 1.6811x; 1.0212x over previous
#include <cuda_runtime.h>
#include <cuda_fp16.h>

#define NN 100000
#define NE 1600000
#define HID 64

// ---- scratch (device globals: allocation-free) ----
__device__ int   g_is64;                          // 1 if edge_index is int64
__device__ __align__(16) int g_esrc[NE];          // dst-sorted src ids
__device__ int   g_cnt[NN];                       // in-degree (excl. self-loop)
__device__ int   g_off[NN];                       // CSR row start
__device__ int   g_cur[NN];                       // bucket cursor
__device__ float g_dinv[NN];                      // 1/sqrt(deg), deg = cnt+1
__device__ int   g_bsum[128];
__device__ __align__(16) __half g_Hh[NN * HID];   // (X@W)*dinv  (fp16 gather copy)
__device__ __align__(16) float  g_XA[NN * HID];   // ping-pong feature buffers
__device__ __align__(16) float  g_XB[NN * HID];

__device__ __forceinline__ int clampi(int v, int hi) {
    return v < 0 ? 0 : (v >= hi ? hi - 1 : v);
}

__device__ __forceinline__ unsigned long long pack2(float f) {
    unsigned long long r;
    asm("mov.b64 %0, {%1, %1};" : "=l"(r) : "f"(f));
    return r;
}
__device__ __forceinline__ unsigned long long ffma2(unsigned long long a,
                                                    unsigned long long b,
                                                    unsigned long long c) {
    unsigned long long d;
    asm("fma.rn.f32x2 %0, %1, %2, %3;" : "=l"(d) : "l"(a), "l"(b), "l"(c));
    return d;
}
__device__ __forceinline__ void unpack2(unsigned long long v, float& lo, float& hi) {
    asm("mov.b64 {%0, %1}, %2;" : "=f"(lo), "=f"(hi) : "l"(v));
}

// ---------------------------------------------------------------------------
// Init: zero counters; block 0 detects edge_index dtype (int64 buffers with
// ids < 2^31 have all-zero odd 32-bit words).
// ---------------------------------------------------------------------------
__global__ void k_init(const unsigned* __restrict__ ei32) {
    int i = blockIdx.x * 256 + threadIdx.x;
    if (i < NN) { g_cnt[i] = 0; g_cur[i] = 0; }
    if (blockIdx.x == 0) {
        int any = 0;
        for (int j = threadIdx.x; j < 2048; j += 256)
            if (ei32[2 * j + 1] != 0u) any = 1;
        any = __syncthreads_or(any);
        if (threadIdx.x == 0) g_is64 = any ? 0 : 1;
    }
}

// 2 edges per thread, 16B loads on the dst column
__global__ void k_count(const void* __restrict__ eiv) {
    int t = blockIdx.x * blockDim.x + threadIdx.x;   // t < NE/2
    if (t >= NE / 2) return;
    int d0, d1;
    if (g_is64) {
        longlong2 p = __ldg(&((const longlong2*)((const long long*)eiv + NE))[t]);
        d0 = (int)p.x; d1 = (int)p.y;
    } else {
        int2 p = __ldg(&((const int2*)((const int*)eiv + NE))[t]);
        d0 = p.x; d1 = p.y;
    }
    atomicAdd(&g_cnt[clampi(d0, NN)], 1);
    atomicAdd(&g_cnt[clampi(d1, NN)], 1);
}

// exclusive scan of g_cnt -> g_off (warp-shuffle scans)
__global__ void k_scan1() {              // grid 98, block 1024
    __shared__ int wsum[32];
    int i    = blockIdx.x * 1024 + threadIdx.x;
    int lane = threadIdx.x & 31, wid = threadIdx.x >> 5;
    int v   = (i < NN) ? g_cnt[i] : 0;
    int inc = v;
#pragma unroll
    for (int o = 1; o < 32; o <<= 1) {
        int t = __shfl_up_sync(0xffffffffu, inc, o);
        if (lane >= o) inc += t;
    }
    if (lane == 31) wsum[wid] = inc;
    __syncthreads();
    if (wid == 0) {
        int s = wsum[lane];
        int si = s;
#pragma unroll
        for (int o = 1; o < 32; o <<= 1) {
            int t = __shfl_up_sync(0xffffffffu, si, o);
            if (lane >= o) si += t;
        }
        wsum[lane] = si - s;                       // exclusive warp prefix
    }
    __syncthreads();
    if (i < NN) g_off[i] = wsum[wid] + inc - v;
    if (threadIdx.x == 1023) g_bsum[blockIdx.x] = wsum[31] + inc;
}

__global__ void k_scan2() {              // 1 block, 128 threads
    __shared__ int wsum[4];
    int lane = threadIdx.x & 31, wid = threadIdx.x >> 5;
    int v   = (threadIdx.x < 98) ? g_bsum[threadIdx.x] : 0;
    int inc = v;
#pragma unroll
    for (int o = 1; o < 32; o <<= 1) {
        int t = __shfl_up_sync(0xffffffffu, inc, o);
        if (lane >= o) inc += t;
    }
    if (lane == 31) wsum[wid] = inc;
    __syncthreads();
    int wpre = 0;
#pragma unroll
    for (int w = 0; w < 4; w++)
        if (w < wid) wpre += wsum[w];
    g_bsum[threadIdx.x] = wpre + inc - v;
}

__global__ void k_scan3() {              // grid 98, block 1024
    int i = blockIdx.x * 1024 + threadIdx.x;
    if (i < NN) {
        g_off[i] += g_bsum[blockIdx.x];
        g_dinv[i] = rsqrtf((float)(g_cnt[i] + 1));
    }
}

__global__ void k_bucket(const void* __restrict__ eiv) {
    int e = blockIdx.x * blockDim.x + threadIdx.x;
    if (e >= NE) return;
    int s, d;
    if (g_is64) {
        const long long* ei = (const long long*)eiv;
        s = (int)ei[e];
        d = (int)ei[NE + e];
    } else {
        const int* ei = (const int*)eiv;
        s = ei[e];
        d = ei[NE + e];
    }
    s = clampi(s, NN);
    d = clampi(d, NN);
    int pos = g_off[d] + atomicAdd(&g_cur[d], 1);
    g_esrc[clampi(pos, NE)] = s;
}

// ---------------------------------------------------------------------------
// GEMM + epilogue:  H = X @ W ;  Hh = (H * dinv) in fp16 for the gather;
//                   Yinit = b + dinv^2 * H + (resid ? X : 0)   (fp32)
// 256 thr/block, 64 rows/block. Thread: 4 rows x 4 cols, FFMA2 packed math.
// ---------------------------------------------------------------------------
__global__ void k_gemm(const float* __restrict__ xext, int xsel,
                       const float* __restrict__ W,
                       const float* __restrict__ bias,
                       int ysel, int resid) {
    const float* xin = (xsel == 0) ? xext : ((xsel == 1) ? g_XA : g_XB);
    float* Y = (ysel == 1) ? g_XA : g_XB;

    __shared__ ulonglong2 sW[HID * 16];              // 16 KB; {cols01, cols23}
    const ulonglong2* Wp = (const ulonglong2*)W;
    for (int i = threadIdx.x; i < HID * 16; i += 256) sW[i] = Wp[i];
    __syncthreads();

    const int cg   = threadIdx.x & 15;               // 4-col group
    const int rq   = threadIdx.x >> 4;               // 0..15
    const int row0 = blockIdx.x * 64 + rq * 4;

    const float4* xr[4];
#pragma unroll
    for (int r = 0; r < 4; r++) {
        int rc = clampi(row0 + r, NN);
        xr[r] = (const float4*)(xin + (size_t)rc * HID);
    }

    unsigned long long a01[4] = {0, 0, 0, 0};        // cols (4cg, 4cg+1)
    unsigned long long a23[4] = {0, 0, 0, 0};        // cols (4cg+2, 4cg+3)

#pragma unroll
    for (int kq = 0; kq < 16; kq++) {
        float4 xv0 = __ldg(&xr[0][kq]);
        float4 xv1 = __ldg(&xr[1][kq]);
        float4 xv2 = __ldg(&xr[2][kq]);
        float4 xv3 = __ldg(&xr[3][kq]);
#define GSTEP(J, C) { \
        ulonglong2 w = sW[(4 * kq + (J)) * 16 + cg]; \
        unsigned long long xx; \
        xx = pack2(xv0.C); a01[0] = ffma2(xx, w.x, a01[0]); a23[0] = ffma2(xx, w.y, a23[0]); \
        xx = pack2(xv1.C); a01[1] = ffma2(xx, w.x, a01[1]); a23[1] = ffma2(xx, w.y, a23[1]); \
        xx = pack2(xv2.C); a01[2] = ffma2(xx, w.x, a01[2]); a23[2] = ffma2(xx, w.y, a23[2]); \
        xx = pack2(xv3.C); a01[3] = ffma2(xx, w.x, a01[3]); a23[3] = ffma2(xx, w.y, a23[3]); }
        GSTEP(0, x) GSTEP(1, y) GSTEP(2, z) GSTEP(3, w)
#undef GSTEP
    }

    const float4 b4 = __ldg(&((const float4*)bias)[cg]);
#pragma unroll
    for (int r = 0; r < 4; r++) {
        int row = row0 + r;
        if (row < NN) {
            float4 h;
            unpack2(a01[r], h.x, h.y);
            unpack2(a23[r], h.z, h.w);
            float dv = g_dinv[row];
            // fp16 pre-scaled copy for the gather: Hh = H * dinv  (one 8B store)
            __half2 p0 = __float22half2_rn(make_float2(h.x * dv, h.y * dv));
            __half2 p1 = __float22half2_rn(make_float2(h.z * dv, h.w * dv));
            uint2 hp;
            hp.x = *(unsigned*)&p0;
            hp.y = *(unsigned*)&p1;
            ((uint2*)g_Hh)[(size_t)row * 16 + cg] = hp;
            // fp32 Y init: bias + self-loop (exact) + residual (exact)
            float d2 = dv * dv;
            float4 y = make_float4(b4.x + h.x * d2, b4.y + h.y * d2,
                                   b4.z + h.z * d2, b4.w + h.w * d2);
            if (resid) {
                float4 xv = __ldg(&xr[r][cg]);   // input is already post-ReLU
                y.x += xv.x; y.y += xv.y; y.z += xv.z; y.w += xv.w;
            }
            ((float4*)Y)[(size_t)row * 16 + cg] = y;
        }
    }
}

// ---------------------------------------------------------------------------
// Aggregate: one warp per node, atomic-free CSR gather (fp16 reads, fp32 acc).
//   a = Yinit[node] + dinv[node] * sum_e Hh[src_e] ;  X = relu(a)
// Final layer (classify=1): out[node] = X @ Wc + bc instead of storing X.
// ---------------------------------------------------------------------------
__global__ void k_agg(int ysel,
                      const float* __restrict__ Wc,
                      const float* __restrict__ bc,
                      float* __restrict__ out, int classify) {
    float* Y = (ysel == 1) ? g_XA : g_XB;
    int gid  = blockIdx.x * blockDim.x + threadIdx.x;
    int node = gid >> 5;
    int lane = gid & 31;

    const int* adj = g_esrc + g_off[node];
    int k = g_cnt[node];
    const __half2* H2 = (const __half2*)g_Hh;

    float2 s = make_float2(0.f, 0.f);
#pragma unroll 8
    for (int j = 0; j < k; j++) {
        int e = __ldg(&adj[j]);                  // broadcast (uniform addr)
        float2 h = __half22float2(__ldg(&H2[(size_t)e * 32 + lane]));
        s.x += h.x;
        s.y += h.y;
    }

    float2 a = ((float2*)Y)[(size_t)node * 32 + lane];
    float dv = g_dinv[node];
    a.x = fmaxf(a.x + dv * s.x, 0.f);
    a.y = fmaxf(a.y + dv * s.y, 0.f);

    if (!classify) {
        ((float2*)Y)[(size_t)node * 32 + lane] = a;
    } else {
        int f = 2 * lane;                        // features f, f+1
        float c0 = a.x * __ldg(&Wc[f * 3 + 0]) + a.y * __ldg(&Wc[f * 3 + 3]);
        float c1 = a.x * __ldg(&Wc[f * 3 + 1]) + a.y * __ldg(&Wc[f * 3 + 4]);
        float c2 = a.x * __ldg(&Wc[f * 3 + 2]) + a.y * __ldg(&Wc[f * 3 + 5]);
#pragma unroll
        for (int o = 16; o > 0; o >>= 1) {
            c0 += __shfl_down_sync(0xffffffffu, c0, o);
            c1 += __shfl_down_sync(0xffffffffu, c1, o);
            c2 += __shfl_down_sync(0xffffffffu, c2, o);
        }
        if (lane == 0) {
            out[node * 3 + 0] = c0 + __ldg(&bc[0]);
            out[node * 3 + 1] = c1 + __ldg(&bc[1]);
            out[node * 3 + 2] = c2 + __ldg(&bc[2]);
        }
    }
}

// ---------------------------------------------------------------------------
extern "C" void kernel_launch(void* const* d_in, const int* in_sizes, int n_in,
                              void* d_out, int out_size) {
    const float* x  = (const float*)d_in[0];
    const void*  ei = d_in[1];
    const float* Ws = (const float*)d_in[2];
    const float* bs = (const float*)d_in[3];
    const float* Wc = (const float*)d_in[4];
    const float* bc = (const float*)d_in[5];
    float* out = (float*)d_out;

    // ---- CSR build ----
    k_init  <<<(NN + 255) / 256, 256>>>((const unsigned*)ei);
    k_count <<<NE / 512, 256>>>(ei);
    k_scan1 <<<98, 1024>>>();
    k_scan2 <<<1, 128>>>();
    k_scan3 <<<98, 1024>>>();
    k_bucket<<<NE / 256, 256>>>(ei);

    // ---- 4 GCN layers (layer 3 fuses the classifier) ----
    const int gemm_grid = (NN + 63) / 64;
    const int agg_grid  = NN * 32 / 256;
    int sel = 0;                                    // 0=x, 1=g_XA, 2=g_XB
    for (int l = 0; l < 4; l++) {
        int osel = (l & 1) ? 2 : 1;
        const float* W = Ws + l * HID * HID;
        const float* b = bs + l * HID;
        k_gemm<<<gemm_grid, 256>>>(x, sel, W, b, osel, (l > 0) ? 1 : 0);
        k_agg <<<agg_grid, 256>>>(osel, Wc, bc, out, (l == 3) ? 1 : 0);
        sel = osel;
    }
}